// round 3
// baseline (speedup 1.0000x reference)
#include <cuda_runtime.h>
#include <cstdint>

// Embedding gather: out[token, :] = weight[input[token], :]
// input: [32768] int32, weight: [50257, 512] f32, out: [32768, 512] f32
//
// One WARP per 2 token rows. Row = 128 float4; thread t handles float4
// columns {t, t+32, t+64, t+96} of BOTH rows -> 8 independent 128B-coalesced
// warp loads front-batched (MLP=8) to hide DRAM/L2 latency. Index loads are
// uniform per warp. Streaming stores (.cs) keep the 67MB write stream
// evict-first in L2 so gathered weight rows stay cached.

__global__ __launch_bounds__(256) void embed_gather_warp2(
    const int* __restrict__ idx,
    const float4* __restrict__ weight4,
    float4* __restrict__ out4,
    int n_tokens)
{
    const int warp_id = (blockIdx.x * blockDim.x + threadIdx.x) >> 5;
    const int lane    = threadIdx.x & 31;
    const int tok0    = warp_id * 2;
    if (tok0 >= n_tokens) return;

    const int row0 = __ldg(idx + tok0);
    const int row1 = __ldg(idx + tok0 + 1);

    const float4* __restrict__ srcA = weight4 + (long long)row0 * 128 + lane;
    const float4* __restrict__ srcB = weight4 + (long long)row1 * 128 + lane;
    float4* __restrict__ dstA = out4 + (long long)tok0 * 128 + lane;
    float4* __restrict__ dstB = dstA + 128;

    // 8 independent loads issued before any store (front-batched MLP=8)
    float4 a0 = __ldg(srcA);
    float4 a1 = __ldg(srcA + 32);
    float4 a2 = __ldg(srcA + 64);
    float4 a3 = __ldg(srcA + 96);
    float4 b0 = __ldg(srcB);
    float4 b1 = __ldg(srcB + 32);
    float4 b2 = __ldg(srcB + 64);
    float4 b3 = __ldg(srcB + 96);

    __stcs(dstA,      a0);
    __stcs(dstA + 32, a1);
    __stcs(dstA + 64, a2);
    __stcs(dstA + 96, a3);
    __stcs(dstB,      b0);
    __stcs(dstB + 32, b1);
    __stcs(dstB + 64, b2);
    __stcs(dstB + 96, b3);
}

extern "C" void kernel_launch(void* const* d_in, const int* in_sizes, int n_in,
                              void* d_out, int out_size) {
    const int*   idx    = (const int*)d_in[0];     // [8*4096] int32
    const float* weight = (const float*)d_in[1];   // [50257*512] f32
    float*       out    = (float*)d_out;

    int n_tokens = in_sizes[0];                    // 32768
    int n_warps  = (n_tokens + 1) / 2;             // 16384
    int threads  = 256;                            // 8 warps/block
    int blocks   = (n_warps * 32 + threads - 1) / threads;  // 2048
    embed_gather_warp2<<<blocks, threads>>>(
        idx, (const float4*)weight, (float4*)out, n_tokens);
}